// round 2
// baseline (speedup 1.0000x reference)
#include <cuda_runtime.h>

// SurfEval: batched NURBS surface evaluation, separable form.
//
// Inputs (metadata order):
//   d_in[0] ctrl : float32 [B=64, M=64, N=64, 4]   (x,y,z,w homogeneous)
//   d_in[1] Nu   : float32 [512, 4]
//   d_in[2] Nv   : float32 [512, 4]
//   d_in[3] iu   : int32   [512, 4]
//   d_in[4] iv   : int32   [512, 4]
// Output:
//   d_out : float32 [B=64, 512, 512, 3]
//
// Math: surf[b,u,v,:] = (sum_{l,r} Nu[u,l]*Nv[v,r]*ctrl[b,iu[u,l],iv[v,r],:])
//       then divide xyz by w.
// Separable: rowcomb[n] = sum_l Nu[u,l]*ctrl[b,iu[u,l],n,:]  (per (b,u) block)
//            out[v]     = sum_r Nv[v,r]*rowcomb[iv[v,r]]

#define B_DIM   64
#define MN_DIM  64
#define U_OUT   512
#define V_OUT   512
#define THREADS 128

__global__ __launch_bounds__(THREADS, 8)
void surfeval_kernel(const float* __restrict__ ctrl,
                     const float* __restrict__ Nu,
                     const float* __restrict__ Nv,
                     const int*   __restrict__ iu,
                     const int*   __restrict__ iv,
                     float*       __restrict__ out)
{
    const int u = blockIdx.x;   // 0..511
    const int b = blockIdx.y;   // 0..63

    __shared__ float4 rowcomb[MN_DIM];   // 1 KB

    // ---- Stage 1: combine the 4 contributing u-rows of ctrl ----
    if (threadIdx.x < MN_DIM) {
        const int n = threadIdx.x;
        // uniform per-block basis weights / indices (broadcast loads, L1-hot)
        const float4 nu  = *reinterpret_cast<const float4*>(Nu + u * 4);
        const int4   iuu = *reinterpret_cast<const int4*>  (iu + u * 4);

        const size_t bbase = (size_t)b * MN_DIM * MN_DIM * 4;
        float4 acc = make_float4(0.f, 0.f, 0.f, 0.f);

        {
            const float4 c = *reinterpret_cast<const float4*>(
                ctrl + bbase + ((size_t)iuu.x * MN_DIM + n) * 4);
            acc.x += nu.x * c.x; acc.y += nu.x * c.y;
            acc.z += nu.x * c.z; acc.w += nu.x * c.w;
        }
        {
            const float4 c = *reinterpret_cast<const float4*>(
                ctrl + bbase + ((size_t)iuu.y * MN_DIM + n) * 4);
            acc.x += nu.y * c.x; acc.y += nu.y * c.y;
            acc.z += nu.y * c.z; acc.w += nu.y * c.w;
        }
        {
            const float4 c = *reinterpret_cast<const float4*>(
                ctrl + bbase + ((size_t)iuu.z * MN_DIM + n) * 4);
            acc.x += nu.z * c.x; acc.y += nu.z * c.y;
            acc.z += nu.z * c.z; acc.w += nu.z * c.w;
        }
        {
            const float4 c = *reinterpret_cast<const float4*>(
                ctrl + bbase + ((size_t)iuu.w * MN_DIM + n) * 4);
            acc.x += nu.w * c.x; acc.y += nu.w * c.y;
            acc.z += nu.w * c.z; acc.w += nu.w * c.w;
        }
        rowcomb[n] = acc;
    }
    __syncthreads();

    // ---- Stage 2: 512 v outputs per block, 4 per thread ----
    const size_t obase = (((size_t)b * U_OUT + u) * V_OUT) * 3;

    #pragma unroll
    for (int it = 0; it < V_OUT / THREADS; ++it) {
        const int v = threadIdx.x + it * THREADS;

        const float4 nv  = *reinterpret_cast<const float4*>(Nv + v * 4);
        const int4   ivv = *reinterpret_cast<const int4*>  (iv + v * 4);

        float4 acc;
        {
            const float4 c = rowcomb[ivv.x];
            acc.x = nv.x * c.x; acc.y = nv.x * c.y;
            acc.z = nv.x * c.z; acc.w = nv.x * c.w;
        }
        {
            const float4 c = rowcomb[ivv.y];
            acc.x += nv.y * c.x; acc.y += nv.y * c.y;
            acc.z += nv.y * c.z; acc.w += nv.y * c.w;
        }
        {
            const float4 c = rowcomb[ivv.z];
            acc.x += nv.z * c.x; acc.y += nv.z * c.y;
            acc.z += nv.z * c.z; acc.w += nv.z * c.w;
        }
        {
            const float4 c = rowcomb[ivv.w];
            acc.x += nv.w * c.x; acc.y += nv.w * c.y;
            acc.z += nv.w * c.z; acc.w += nv.w * c.w;
        }

        const float inv = __fdividef(1.0f, acc.w);
        const size_t o = obase + (size_t)v * 3;
        out[o + 0] = acc.x * inv;
        out[o + 1] = acc.y * inv;
        out[o + 2] = acc.z * inv;
    }
}

extern "C" void kernel_launch(void* const* d_in, const int* in_sizes, int n_in,
                              void* d_out, int out_size)
{
    const float* ctrl = (const float*)d_in[0];
    const float* Nu   = (const float*)d_in[1];
    const float* Nv   = (const float*)d_in[2];
    const int*   iu   = (const int*)  d_in[3];
    const int*   iv   = (const int*)  d_in[4];
    float*       out  = (float*)d_out;

    dim3 grid(U_OUT, B_DIM);
    surfeval_kernel<<<grid, THREADS>>>(ctrl, Nu, Nv, iu, iv, out);
}

// round 5
// speedup vs baseline: 1.0228x; 1.0228x over previous
#include <cuda_runtime.h>
#include <cstdint>

// SurfEval: batched NURBS surface evaluation, separable form + smem-staged
// bulk-async output stores.
//
// Inputs (metadata order):
//   d_in[0] ctrl : float32 [B=64, M=64, N=64, 4]   (x,y,z,w homogeneous)
//   d_in[1] Nu   : float32 [512, 4]
//   d_in[2] Nv   : float32 [512, 4]
//   d_in[3] iu   : int32   [512, 4]
//   d_in[4] iv   : int32   [512, 4]
// Output:
//   d_out : float32 [B=64, 512, 512, 3]
//
// Per block (b,u):
//   Stage 1: rowcomb[n] = sum_l Nu[u,l] * ctrl[b, iu[u,l], n, :]     (smem, 1 KB)
//   Stage 2: out[v]     = sum_r Nv[v,r] * rowcomb[iv[v,r]]; xyz/w    -> smem (6 KB)
//   Stage 3: one cp.async.bulk shared->global of the 6144-byte row.

#define B_DIM   64
#define MN_DIM  64
#define U_OUT   512
#define V_OUT   512
#define THREADS 128

__device__ __forceinline__ uint32_t smem_u32(const void* p) {
    uint32_t a;
    asm("{ .reg .u64 t; cvta.to.shared.u64 t, %1; cvt.u32.u64 %0, t; }"
        : "=r"(a) : "l"(p));
    return a;
}

__global__ __launch_bounds__(THREADS, 8)
void surfeval_kernel(const float* __restrict__ ctrl,
                     const float* __restrict__ Nu,
                     const float* __restrict__ Nv,
                     const int*   __restrict__ iu,
                     const int*   __restrict__ iv,
                     float*       __restrict__ out)
{
    const int u = blockIdx.x;   // 0..511
    const int b = blockIdx.y;   // 0..63

    __shared__ float4 rowcomb[MN_DIM];                      // 1 KB
    __shared__ __align__(16) float outbuf[V_OUT * 3];       // 6 KB

    // ---- Stage 1: combine the 4 contributing u-rows of ctrl ----
    if (threadIdx.x < MN_DIM) {
        const int n = threadIdx.x;
        const float4 nu  = *reinterpret_cast<const float4*>(Nu + u * 4);
        const int4   iuu = *reinterpret_cast<const int4*>  (iu + u * 4);

        const size_t bbase = (size_t)b * MN_DIM * MN_DIM * 4;

        const float4 c0 = *reinterpret_cast<const float4*>(
            ctrl + bbase + ((size_t)iuu.x * MN_DIM + n) * 4);
        const float4 c1 = *reinterpret_cast<const float4*>(
            ctrl + bbase + ((size_t)iuu.y * MN_DIM + n) * 4);
        const float4 c2 = *reinterpret_cast<const float4*>(
            ctrl + bbase + ((size_t)iuu.z * MN_DIM + n) * 4);
        const float4 c3 = *reinterpret_cast<const float4*>(
            ctrl + bbase + ((size_t)iuu.w * MN_DIM + n) * 4);

        float4 acc;
        acc.x = nu.x*c0.x + nu.y*c1.x + nu.z*c2.x + nu.w*c3.x;
        acc.y = nu.x*c0.y + nu.y*c1.y + nu.z*c2.y + nu.w*c3.y;
        acc.z = nu.x*c0.z + nu.y*c1.z + nu.z*c2.z + nu.w*c3.z;
        acc.w = nu.x*c0.w + nu.y*c1.w + nu.z*c2.w + nu.w*c3.w;
        rowcomb[n] = acc;
    }
    __syncthreads();

    // ---- Stage 2: 512 v points -> smem staging buffer ----
    #pragma unroll
    for (int it = 0; it < V_OUT / THREADS; ++it) {
        const int v = threadIdx.x + it * THREADS;

        const float4 nv  = *reinterpret_cast<const float4*>(Nv + v * 4);
        const int4   ivv = *reinterpret_cast<const int4*>  (iv + v * 4);

        const float4 c0 = rowcomb[ivv.x];
        const float4 c1 = rowcomb[ivv.y];
        const float4 c2 = rowcomb[ivv.z];
        const float4 c3 = rowcomb[ivv.w];

        float ax = nv.x*c0.x + nv.y*c1.x + nv.z*c2.x + nv.w*c3.x;
        float ay = nv.x*c0.y + nv.y*c1.y + nv.z*c2.y + nv.w*c3.y;
        float az = nv.x*c0.z + nv.y*c1.z + nv.z*c2.z + nv.w*c3.z;
        float aw = nv.x*c0.w + nv.y*c1.w + nv.z*c2.w + nv.w*c3.w;

        const float inv = __fdividef(1.0f, aw);
        // STS.32 x3, lane address stride = 3 words, gcd(3,32)=1 -> conflict-free
        outbuf[v * 3 + 0] = ax * inv;
        outbuf[v * 3 + 1] = ay * inv;
        outbuf[v * 3 + 2] = az * inv;
    }
    __syncthreads();

    // ---- Stage 3: single bulk-async store of the whole 6144-byte row ----
    if (threadIdx.x == 0) {
        // Order generic-proxy STS above against the async-proxy bulk read.
        asm volatile("fence.proxy.async.shared::cta;" ::: "memory");

        float* gdst = out + (((size_t)b * U_OUT + u) * V_OUT) * 3;
        const uint32_t src = smem_u32(outbuf);
        asm volatile(
            "cp.async.bulk.global.shared::cta.bulk_group [%0], [%1], %2;"
            :: "l"(gdst), "r"(src), "n"(V_OUT * 3 * 4)
            : "memory");
        asm volatile("cp.async.bulk.commit_group;" ::: "memory");
        asm volatile("cp.async.bulk.wait_group 0;" ::: "memory");
    }
}

extern "C" void kernel_launch(void* const* d_in, const int* in_sizes, int n_in,
                              void* d_out, int out_size)
{
    const float* ctrl = (const float*)d_in[0];
    const float* Nu   = (const float*)d_in[1];
    const float* Nv   = (const float*)d_in[2];
    const int*   iu   = (const int*)  d_in[3];
    const int*   iv   = (const int*)  d_in[4];
    float*       out  = (float*)d_out;

    dim3 grid(U_OUT, B_DIM);
    surfeval_kernel<<<grid, THREADS>>>(ctrl, Nu, Nv, iu, iv, out);
}

// round 7
// speedup vs baseline: 1.3146x; 1.2852x over previous
#include <cuda_runtime.h>
#include <cstdint>

// SurfEval: batched NURBS surface evaluation.
//
// Inputs (metadata order):
//   d_in[0] ctrl : float32 [B=64, M=64, N=64, 4]
//   d_in[1] Nu   : float32 [512, 4]
//   d_in[2] Nv   : float32 [512, 4]
//   d_in[3] iu   : int32   [512, 4]
//   d_in[4] iv   : int32   [512, 4]
// Output: d_out : float32 [B=64, 512, 512, 3]
//
// Block = (b, 8 consecutive u rows), 256 threads.
//   Stage 1: rc[r][n] = sum_l Nu[u,l] * ctrl[b, iu[u,l], n, :]   (8 KB smem)
//   Setup  : per-thread 4-v group; 5-wide span-window weights W in registers
//            (iv[v,r] for 4 consecutive v spans at most [bmin..bmin+4])
//   Stage 2: per row: 5 LDS.128 gathers + FMAs + 3 STS.128 into a
//            double-buffered row, then one cp.async.bulk (6144 B) per row.

#define MN_DIM  64
#define U_OUT   512
#define V_OUT   512
#define RPB     8      // u-rows per block
#define THREADS 256

__device__ __forceinline__ uint32_t smem_u32(const void* p) {
    uint32_t a;
    asm("{ .reg .u64 t; cvta.to.shared.u64 t, %1; cvt.u32.u64 %0, t; }"
        : "=r"(a) : "l"(p));
    return a;
}

__global__ __launch_bounds__(THREADS)
void surfeval_kernel(const float* __restrict__ ctrl,
                     const float* __restrict__ Nu,
                     const float* __restrict__ Nv,
                     const int*   __restrict__ iu,
                     const int*   __restrict__ iv,
                     float*       __restrict__ out)
{
    const int u0 = blockIdx.x * RPB;   // 0,8,...,504
    const int b  = blockIdx.y;         // 0..63

    __shared__ float4 rc[RPB][MN_DIM];                         // 8 KB
    __shared__ __align__(16) float outbuf[2][2][V_OUT * 3];    // 24 KB

    const int tid = threadIdx.x;

    // ---- Stage 1: rowcomb for 8 rows (2 entries per thread) ----
    {
        const int n  = tid & 63;
        const int r0 = tid >> 6;   // 0..3
        const float4* __restrict__ cb =
            reinterpret_cast<const float4*>(ctrl) + (size_t)b * MN_DIM * MN_DIM;

        #pragma unroll
        for (int i = 0; i < 2; ++i) {
            const int r = r0 + 4 * i;
            const int u = u0 + r;
            const float4 nu  = *reinterpret_cast<const float4*>(Nu + u * 4);
            const int4   iuu = *reinterpret_cast<const int4*>  (iu + u * 4);

            const float4 c0 = cb[iuu.x * MN_DIM + n];
            const float4 c1 = cb[iuu.y * MN_DIM + n];
            const float4 c2 = cb[iuu.z * MN_DIM + n];
            const float4 c3 = cb[iuu.w * MN_DIM + n];

            float4 acc;
            acc.x = nu.x*c0.x + nu.y*c1.x + nu.z*c2.x + nu.w*c3.x;
            acc.y = nu.x*c0.y + nu.y*c1.y + nu.z*c2.y + nu.w*c3.y;
            acc.z = nu.x*c0.z + nu.y*c1.z + nu.z*c2.z + nu.w*c3.z;
            acc.w = nu.x*c0.w + nu.y*c1.w + nu.z*c2.w + nu.w*c3.w;
            rc[r][n] = acc;
        }
    }

    // ---- Per-thread v-group setup (once per block) ----
    const int vg   = tid & 127;    // v-group id
    const int half = tid >> 7;     // which row of the pair this thread works on
    const int v0   = vg * 4;

    // 5-wide window weights: out[v] = sum_k W[j][k] * rc[bmin + k]
    float W[4][5];
    const int bmin = iv[v0 * 4];   // iv[v0][0] = span(v0) - 3
    #pragma unroll
    for (int j = 0; j < 4; ++j) {
        const int v = v0 + j;
        const float4 nv = *reinterpret_cast<const float4*>(Nv + v * 4);
        const int d = iv[v * 4] - bmin;   // 0 or 1 (span len >= 8 > 4)
        W[j][0] = d ? 0.f  : nv.x;
        W[j][1] = d ? nv.x : nv.y;
        W[j][2] = d ? nv.y : nv.z;
        W[j][3] = d ? nv.z : nv.w;
        W[j][4] = d ? nv.w : 0.f;
    }

    __syncthreads();   // rc ready

    // ---- Stage 2: 4 iterations x 2 rows, double-buffered TMA stores ----
    #pragma unroll
    for (int it = 0; it < 4; ++it) {
        const int row = 2 * it + half;
        const int buf = it & 1;

        if (it >= 2) {
            if (vg == 0)   // per-issuer bulk group: buffer (it&1) drained
                asm volatile("cp.async.bulk.wait_group 1;" ::: "memory");
            __syncthreads();
        }

        const float4* rcp = &rc[row][bmin];
        const float4 g0 = rcp[0];
        const float4 g1 = rcp[1];
        const float4 g2 = rcp[2];
        const float4 g3 = rcp[3];
        const float4 g4 = rcp[4];

        float ov[12];
        #pragma unroll
        for (int j = 0; j < 4; ++j) {
            const float x = W[j][0]*g0.x + W[j][1]*g1.x + W[j][2]*g2.x
                          + W[j][3]*g3.x + W[j][4]*g4.x;
            const float y = W[j][0]*g0.y + W[j][1]*g1.y + W[j][2]*g2.y
                          + W[j][3]*g3.y + W[j][4]*g4.y;
            const float z = W[j][0]*g0.z + W[j][1]*g1.z + W[j][2]*g2.z
                          + W[j][3]*g3.z + W[j][4]*g4.z;
            const float w = W[j][0]*g0.w + W[j][1]*g1.w + W[j][2]*g2.w
                          + W[j][3]*g3.w + W[j][4]*g4.w;
            const float inv = __fdividef(1.0f, w);
            ov[3*j + 0] = x * inv;
            ov[3*j + 1] = y * inv;
            ov[3*j + 2] = z * inv;
        }

        // 48 contiguous bytes per thread -> 3 STS.128
        float4* ob = reinterpret_cast<float4*>(&outbuf[buf][half][v0 * 3]);
        ob[0] = make_float4(ov[0], ov[1], ov[2],  ov[3]);
        ob[1] = make_float4(ov[4], ov[5], ov[6],  ov[7]);
        ob[2] = make_float4(ov[8], ov[9], ov[10], ov[11]);

        __syncthreads();

        if (vg == 0) {   // tid 0 -> half 0 row, tid 128 -> half 1 row
            asm volatile("fence.proxy.async.shared::cta;" ::: "memory");
            float* gdst = out + (((size_t)b * U_OUT + u0 + row) * V_OUT) * 3;
            const uint32_t src = smem_u32(&outbuf[buf][half][0]);
            asm volatile(
                "cp.async.bulk.global.shared::cta.bulk_group [%0], [%1], %2;"
                :: "l"(gdst), "r"(src), "n"(V_OUT * 3 * 4)
                : "memory");
            asm volatile("cp.async.bulk.commit_group;" ::: "memory");
        }
    }

    // Drain outstanding bulk copies before smem is released.
    if (vg == 0)
        asm volatile("cp.async.bulk.wait_group 0;" ::: "memory");
}

extern "C" void kernel_launch(void* const* d_in, const int* in_sizes, int n_in,
                              void* d_out, int out_size)
{
    const float* ctrl = (const float*)d_in[0];
    const float* Nu   = (const float*)d_in[1];
    const float* Nv   = (const float*)d_in[2];
    const int*   iu   = (const int*)  d_in[3];
    const int*   iv   = (const int*)  d_in[4];
    float*       out  = (float*)d_out;

    dim3 grid(U_OUT / RPB, 64);
    surfeval_kernel<<<grid, THREADS>>>(ctrl, Nu, Nv, iu, iv, out);
}

// round 12
// speedup vs baseline: 1.7708x; 1.3471x over previous
#include <cuda_runtime.h>
#include <cstdint>

// SurfEval: batched NURBS surface evaluation.
//
// Inputs (metadata order):
//   d_in[0] ctrl : float32 [B=64, M=64, N=64, 4]
//   d_in[1] Nu   : float32 [512, 4]
//   d_in[2] Nv   : float32 [512, 4]
//   d_in[3] iu   : int32   [512, 4]
//   d_in[4] iv   : int32   [512, 4]
// Output: d_out : float32 [B=64, 512, 512, 3]
//
// Kernel 1 (once): build 5-wide span-window weights for each 4-v group,
//   stored TRANSPOSED ([j*5+k][group]) so the main kernel reads them with
//   fully coalesced 1-wavefront LDG.32s.
// Kernel 2 (main): block = (b, 8 u-rows), 128 threads, thread = one 4-v group.
//   Stage 1: rc[r][n] = sum_l Nu[u,l] * ctrl[b, iu[u,l], n, :]   (8 KB smem)
//   Stage 2 (8 its, one row each): 5 LDS.128 window gather + FMA + 3 STS.128
//     into double-buffered 6144-B row; one cp.async.bulk per row, ping-pong.

#define MN_DIM  64
#define U_OUT   512
#define V_OUT   512
#define RPB     8
#define THREADS 128
#define NGROUPS 128   // 4-v groups

__device__ float g_Wt[20][NGROUPS];   // [j*5+k][group]
__device__ int   g_bmin[NGROUPS];

__global__ void precompute_w(const float* __restrict__ Nv,
                             const int*   __restrict__ iv)
{
    const int g  = threadIdx.x;        // 0..127
    const int v0 = g * 4;
    const int bmin = iv[v0 * 4];       // iv[v0][0] = span(v0) - 3
    g_bmin[g] = bmin;

    #pragma unroll
    for (int j = 0; j < 4; ++j) {
        const int v = v0 + j;
        const float4 nv = *reinterpret_cast<const float4*>(Nv + v * 4);
        const int d = iv[v * 4] - bmin;   // 0 or 1 (span length >= 8 > 4)
        float w[5];
        w[0] = d ? 0.f  : nv.x;
        w[1] = d ? nv.x : nv.y;
        w[2] = d ? nv.y : nv.z;
        w[3] = d ? nv.z : nv.w;
        w[4] = d ? nv.w : 0.f;
        #pragma unroll
        for (int k = 0; k < 5; ++k)
            g_Wt[j * 5 + k][g] = w[k];
    }
}

__device__ __forceinline__ uint32_t smem_u32(const void* p) {
    uint32_t a;
    asm("{ .reg .u64 t; cvta.to.shared.u64 t, %1; cvt.u32.u64 %0, t; }"
        : "=r"(a) : "l"(p));
    return a;
}

__global__ __launch_bounds__(THREADS, 8)
void surfeval_kernel(const float* __restrict__ ctrl,
                     const float* __restrict__ Nu,
                     const int*   __restrict__ iu,
                     float*       __restrict__ out)
{
    const int u0 = blockIdx.x * RPB;   // 0,8,...,504
    const int b  = blockIdx.y;         // 0..63
    const int tid = threadIdx.x;       // == v-group id

    __shared__ float4 rc[RPB][MN_DIM];                      // 8 KB
    __shared__ __align__(16) float outbuf[2][V_OUT * 3];    // 12 KB

    // ---- Coalesced weight fetch (1 wavefront per LDG.32) ----
    float W[4][5];
    #pragma unroll
    for (int j = 0; j < 4; ++j)
        #pragma unroll
        for (int k = 0; k < 5; ++k)
            W[j][k] = g_Wt[j * 5 + k][tid];
    const int bmin = g_bmin[tid];

    // ---- Stage 1: rowcomb for 8 rows (4 entries per thread) ----
    {
        const float4* __restrict__ cb =
            reinterpret_cast<const float4*>(ctrl) + (size_t)b * MN_DIM * MN_DIM;

        #pragma unroll
        for (int i = 0; i < 4; ++i) {
            const int e = tid + THREADS * i;   // 0..511
            const int r = e >> 6;              // row 0..7
            const int n = e & 63;
            const int u = u0 + r;
            // warp-uniform basis/index loads (broadcast)
            const float4 nu  = *reinterpret_cast<const float4*>(Nu + u * 4);
            const int4   iuu = *reinterpret_cast<const int4*>  (iu + u * 4);

            const float4 c0 = cb[iuu.x * MN_DIM + n];
            const float4 c1 = cb[iuu.y * MN_DIM + n];
            const float4 c2 = cb[iuu.z * MN_DIM + n];
            const float4 c3 = cb[iuu.w * MN_DIM + n];

            float4 acc;
            acc.x = nu.x*c0.x + nu.y*c1.x + nu.z*c2.x + nu.w*c3.x;
            acc.y = nu.x*c0.y + nu.y*c1.y + nu.z*c2.y + nu.w*c3.y;
            acc.z = nu.x*c0.z + nu.y*c1.z + nu.z*c2.z + nu.w*c3.z;
            acc.w = nu.x*c0.w + nu.y*c1.w + nu.z*c2.w + nu.w*c3.w;
            rc[r][n] = acc;
        }
    }
    __syncthreads();

    // ---- Stage 2: 8 rows, double-buffered bulk stores ----
    #pragma unroll
    for (int it = 0; it < RPB; ++it) {
        const int buf = it & 1;

        if (it >= 2) {
            if (tid == 0)   // group from it-2 must be drained before reuse
                asm volatile("cp.async.bulk.wait_group 1;" ::: "memory");
            __syncthreads();
        }

        const float4* rcp = &rc[it][bmin];
        const float4 g0 = rcp[0];
        const float4 g1 = rcp[1];
        const float4 g2 = rcp[2];
        const float4 g3 = rcp[3];
        const float4 g4 = rcp[4];

        float ov[12];
        #pragma unroll
        for (int j = 0; j < 4; ++j) {
            const float x = W[j][0]*g0.x + W[j][1]*g1.x + W[j][2]*g2.x
                          + W[j][3]*g3.x + W[j][4]*g4.x;
            const float y = W[j][0]*g0.y + W[j][1]*g1.y + W[j][2]*g2.y
                          + W[j][3]*g3.y + W[j][4]*g4.y;
            const float z = W[j][0]*g0.z + W[j][1]*g1.z + W[j][2]*g2.z
                          + W[j][3]*g3.z + W[j][4]*g4.z;
            const float w = W[j][0]*g0.w + W[j][1]*g1.w + W[j][2]*g2.w
                          + W[j][3]*g3.w + W[j][4]*g4.w;
            const float inv = __fdividef(1.0f, w);
            ov[3*j + 0] = x * inv;
            ov[3*j + 1] = y * inv;
            ov[3*j + 2] = z * inv;
        }

        // 48 contiguous bytes per thread -> 3 STS.128
        float4* ob = reinterpret_cast<float4*>(&outbuf[buf][tid * 12]);
        ob[0] = make_float4(ov[0], ov[1], ov[2],  ov[3]);
        ob[1] = make_float4(ov[4], ov[5], ov[6],  ov[7]);
        ob[2] = make_float4(ov[8], ov[9], ov[10], ov[11]);

        __syncthreads();

        if (tid == 0) {
            asm volatile("fence.proxy.async.shared::cta;" ::: "memory");
            float* gdst = out + (((size_t)b * U_OUT + u0 + it) * V_OUT) * 3;
            const uint32_t src = smem_u32(&outbuf[buf][0]);
            asm volatile(
                "cp.async.bulk.global.shared::cta.bulk_group [%0], [%1], %2;"
                :: "l"(gdst), "r"(src), "n"(V_OUT * 3 * 4)
                : "memory");
            asm volatile("cp.async.bulk.commit_group;" ::: "memory");
        }
    }

    // Drain before CTA retires (tid 0 holds the CTA alive).
    if (tid == 0)
        asm volatile("cp.async.bulk.wait_group 0;" ::: "memory");
}

extern "C" void kernel_launch(void* const* d_in, const int* in_sizes, int n_in,
                              void* d_out, int out_size)
{
    const float* ctrl = (const float*)d_in[0];
    const float* Nu   = (const float*)d_in[1];
    const float* Nv   = (const float*)d_in[2];
    const int*   iu   = (const int*)  d_in[3];
    const int*   iv   = (const int*)  d_in[4];
    float*       out  = (float*)d_out;

    precompute_w<<<1, NGROUPS>>>(Nv, iv);

    dim3 grid(U_OUT / RPB, 64);
    surfeval_kernel<<<grid, THREADS>>>(ctrl, Nu, iu, out);
}

// round 14
// speedup vs baseline: 1.7823x; 1.0065x over previous
#include <cuda_runtime.h>
#include <cstdint>

// SurfEval: batched NURBS surface evaluation.
//
// Inputs (metadata order):
//   d_in[0] ctrl : float32 [B=64, M=64, N=64, 4]
//   d_in[1] Nu   : float32 [512, 4]
//   d_in[2] Nv   : float32 [512, 4]
//   d_in[3] iu   : int32   [512, 4]
//   d_in[4] iv   : int32   [512, 4]
// Output: d_out : float32 [B=64, 512, 512, 3]
//
// Kernel 1 (once): 5-wide span-window weights per 4-v group, transposed for
//   coalesced fetch.
// Kernel 2: block = (b, 8 u-rows), 128 threads; thread = one 4-v group.
//   Stage 1: rc[r][n] = sum_l Nu[u,l]*ctrl[b,iu[u,l],n,:]  (8 KB smem) + 1 BAR
//   Stage 2: per-warp decoupled: each warp stages its 1536-B row slice in a
//   private double buffer and lane 0 issues cp.async.bulk per row; only
//   __syncwarp ordering, no block barriers.

#define MN_DIM  64
#define U_OUT   512
#define V_OUT   512
#define RPB     8
#define THREADS 128
#define NGROUPS 128            // 4-v groups
#define WSLICE  (V_OUT * 3 / 4)   // 384 floats = 1536 B per warp per row

__device__ float g_Wt[20][NGROUPS];   // [j*5+k][group]
__device__ int   g_bmin[NGROUPS];

__global__ void precompute_w(const float* __restrict__ Nv,
                             const int*   __restrict__ iv)
{
    const int g  = threadIdx.x;        // 0..127
    const int v0 = g * 4;
    const int bmin = iv[v0 * 4];       // iv[v0][0] = span(v0) - 3
    g_bmin[g] = bmin;

    #pragma unroll
    for (int j = 0; j < 4; ++j) {
        const int v = v0 + j;
        const float4 nv = *reinterpret_cast<const float4*>(Nv + v * 4);
        const int d = iv[v * 4] - bmin;   // 0 or 1 (span length >= 8 > 4)
        float w[5];
        w[0] = d ? 0.f  : nv.x;
        w[1] = d ? nv.x : nv.y;
        w[2] = d ? nv.y : nv.z;
        w[3] = d ? nv.z : nv.w;
        w[4] = d ? nv.w : 0.f;
        #pragma unroll
        for (int k = 0; k < 5; ++k)
            g_Wt[j * 5 + k][g] = w[k];
    }
}

__device__ __forceinline__ uint32_t smem_u32(const void* p) {
    uint32_t a;
    asm("{ .reg .u64 t; cvta.to.shared.u64 t, %1; cvt.u32.u64 %0, t; }"
        : "=r"(a) : "l"(p));
    return a;
}

__global__ __launch_bounds__(THREADS, 8)
void surfeval_kernel(const float* __restrict__ ctrl,
                     const float* __restrict__ Nu,
                     const int*   __restrict__ iu,
                     float*       __restrict__ out)
{
    const int u0   = blockIdx.x * RPB;   // 0,8,...,504
    const int b    = blockIdx.y;         // 0..63
    const int tid  = threadIdx.x;        // == v-group id
    const int warp = tid >> 5;
    const int lane = tid & 31;

    __shared__ float4 rc[RPB][MN_DIM];                          // 8 KB
    __shared__ __align__(16) float outbuf[2][4][WSLICE];        // 12 KB

    // ---- Coalesced weight fetch (1 wavefront per LDG.32) ----
    float W[4][5];
    #pragma unroll
    for (int j = 0; j < 4; ++j)
        #pragma unroll
        for (int k = 0; k < 5; ++k)
            W[j][k] = g_Wt[j * 5 + k][tid];
    const int bmin = g_bmin[tid];

    // ---- Stage 1: rowcomb for 8 rows (4 entries per thread) ----
    {
        const float4* __restrict__ cb =
            reinterpret_cast<const float4*>(ctrl) + (size_t)b * MN_DIM * MN_DIM;

        #pragma unroll
        for (int i = 0; i < 4; ++i) {
            const int e = tid + THREADS * i;   // 0..511
            const int r = e >> 6;              // row 0..7
            const int n = e & 63;
            const int u = u0 + r;
            const float4 nu  = *reinterpret_cast<const float4*>(Nu + u * 4);
            const int4   iuu = *reinterpret_cast<const int4*>  (iu + u * 4);

            const float4 c0 = cb[iuu.x * MN_DIM + n];
            const float4 c1 = cb[iuu.y * MN_DIM + n];
            const float4 c2 = cb[iuu.z * MN_DIM + n];
            const float4 c3 = cb[iuu.w * MN_DIM + n];

            float4 acc;
            acc.x = nu.x*c0.x + nu.y*c1.x + nu.z*c2.x + nu.w*c3.x;
            acc.y = nu.x*c0.y + nu.y*c1.y + nu.z*c2.y + nu.w*c3.y;
            acc.z = nu.x*c0.z + nu.y*c1.z + nu.z*c2.z + nu.w*c3.z;
            acc.w = nu.x*c0.w + nu.y*c1.w + nu.z*c2.w + nu.w*c3.w;
            rc[r][n] = acc;
        }
    }
    __syncthreads();   // rc ready; read-only from here on

    // ---- Stage 2: 8 rows, per-warp double-buffered bulk stores ----
    // Warp owns bytes [warp*1536, warp*1536+1536) of each 6144-B output row.
    const size_t rowbase = (((size_t)b * U_OUT + u0) * V_OUT) * 3 + warp * WSLICE;

    #pragma unroll
    for (int it = 0; it < RPB; ++it) {
        const int buf = it & 1;

        if (it >= 2) {
            // this warp's copy from iteration it-2 must be drained
            if (lane == 0)
                asm volatile("cp.async.bulk.wait_group 1;" ::: "memory");
            __syncwarp();
        }

        const float4* rcp = &rc[it][bmin];
        const float4 g0 = rcp[0];
        const float4 g1 = rcp[1];
        const float4 g2 = rcp[2];
        const float4 g3 = rcp[3];
        const float4 g4 = rcp[4];

        float ov[12];
        #pragma unroll
        for (int j = 0; j < 4; ++j) {
            const float x = W[j][0]*g0.x + W[j][1]*g1.x + W[j][2]*g2.x
                          + W[j][3]*g3.x + W[j][4]*g4.x;
            const float y = W[j][0]*g0.y + W[j][1]*g1.y + W[j][2]*g2.y
                          + W[j][3]*g3.y + W[j][4]*g4.y;
            const float z = W[j][0]*g0.z + W[j][1]*g1.z + W[j][2]*g2.z
                          + W[j][3]*g3.z + W[j][4]*g4.z;
            const float w = W[j][0]*g0.w + W[j][1]*g1.w + W[j][2]*g2.w
                          + W[j][3]*g3.w + W[j][4]*g4.w;
            const float inv = __fdividef(1.0f, w);
            ov[3*j + 0] = x * inv;
            ov[3*j + 1] = y * inv;
            ov[3*j + 2] = z * inv;
        }

        // 48 contiguous bytes per lane -> 3 STS.128
        float4* ob = reinterpret_cast<float4*>(&outbuf[buf][warp][lane * 12]);
        ob[0] = make_float4(ov[0], ov[1], ov[2],  ov[3]);
        ob[1] = make_float4(ov[4], ov[5], ov[6],  ov[7]);
        ob[2] = make_float4(ov[8], ov[9], ov[10], ov[11]);

        __syncwarp();

        if (lane == 0) {
            // order this warp's generic-proxy STS against the async-proxy read
            asm volatile("fence.proxy.async.shared::cta;" ::: "memory");
            float* gdst = out + rowbase + (size_t)it * (V_OUT * 3);
            const uint32_t src = smem_u32(&outbuf[buf][warp][0]);
            asm volatile(
                "cp.async.bulk.global.shared::cta.bulk_group [%0], [%1], %2;"
                :: "l"(gdst), "r"(src), "n"(WSLICE * 4)
                : "memory");
            asm volatile("cp.async.bulk.commit_group;" ::: "memory");
        }
        __syncwarp();
    }

    // Drain this warp's outstanding copies before the CTA can retire.
    if (lane == 0)
        asm volatile("cp.async.bulk.wait_group 0;" ::: "memory");
}

extern "C" void kernel_launch(void* const* d_in, const int* in_sizes, int n_in,
                              void* d_out, int out_size)
{
    const float* ctrl = (const float*)d_in[0];
    const float* Nu   = (const float*)d_in[1];
    const float* Nv   = (const float*)d_in[2];
    const int*   iu   = (const int*)  d_in[3];
    const int*   iv   = (const int*)  d_in[4];
    float*       out  = (float*)d_out;

    precompute_w<<<1, NGROUPS>>>(Nv, iv);

    dim3 grid(U_OUT / RPB, 64);
    surfeval_kernel<<<grid, THREADS>>>(ctrl, Nu, iu, out);
}